// round 4
// baseline (speedup 1.0000x reference)
#include <cuda_runtime.h>
#include <math.h>

#define BB 32
#define CC 256
#define HWD 96
#define ROW4 (HWD/4)         // 24 float4 per row
#define PLANE (HWD*HWD)      // 9216
#define NPLANES (BB*CC)      // 8192
#define KK 9
#define W2ROWS (CC*KK)       // 2304

// scratch (no allocations allowed)
__device__ float g_pooled[BB*CC];
__device__ float g_wdyn[BB*CC*KK];

// ---------------------------------------------------------------------------
// Kernel 1: global average pool per (b,c) plane. 1 block = 1 plane.
// Measured at ~84% DRAM roofline already.
// ---------------------------------------------------------------------------
__global__ __launch_bounds__(256) void pool_kernel(const float* __restrict__ x) {
    const int plane = blockIdx.x;
    const float4* __restrict__ xp =
        reinterpret_cast<const float4*>(x + (size_t)plane * PLANE);
    float sum = 0.f;
#pragma unroll
    for (int it = 0; it < 9; ++it) {               // 9216/4/256 = 9
        float4 v = xp[threadIdx.x + it * 256];
        sum += (v.x + v.y) + (v.z + v.w);
    }
#pragma unroll
    for (int o = 16; o > 0; o >>= 1)
        sum += __shfl_xor_sync(0xffffffffu, sum, o);
    __shared__ float ws[8];
    const int lane = threadIdx.x & 31, wid = threadIdx.x >> 5;
    if (lane == 0) ws[wid] = sum;
    __syncthreads();
    if (threadIdx.x == 0) {
        float t = 0.f;
#pragma unroll
        for (int i = 0; i < 8; ++i) t += ws[i];
        g_pooled[plane] = t * (1.0f / (float)PLANE);
    }
}

// ---------------------------------------------------------------------------
// Kernel 2: dynamic net, parallelized. grid = (9, 32).
// Block (r0, b): recompute h = gelu(pooled[b] @ w1^T + b1) (cheap),
// each thread then computes one row r = r0*256+tid of wdyn[b].
// ---------------------------------------------------------------------------
__global__ __launch_bounds__(256) void dyn_kernel(const float* __restrict__ w1,
                                                  const float* __restrict__ b1,
                                                  const float* __restrict__ w2,
                                                  const float* __restrict__ b2) {
    const int b  = blockIdx.y;
    const int r0 = blockIdx.x;
    const int c  = threadIdx.x;
    __shared__ float ps[CC];
    __shared__ float hs[CC];
    ps[c] = g_pooled[b * CC + c];
    __syncthreads();

    {
        float acc = b1[c];
        const float4* __restrict__ wr =
            reinterpret_cast<const float4*>(w1 + (size_t)c * CC);
        const float4* __restrict__ pv = reinterpret_cast<const float4*>(ps);
#pragma unroll 8
        for (int k = 0; k < CC / 4; ++k) {
            float4 a = pv[k];
            float4 w = wr[k];
            acc += a.x * w.x + a.y * w.y + a.z * w.z + a.w * w.w;
        }
        hs[c] = 0.5f * acc * (1.0f + erff(acc * 0.70710678118654752f));
    }
    __syncthreads();

    const int r = r0 * 256 + c;
    float acc = b2[r];
    const float4* __restrict__ wr =
        reinterpret_cast<const float4*>(w2 + (size_t)r * CC);
    const float4* __restrict__ hv = reinterpret_cast<const float4*>(hs);
#pragma unroll 8
    for (int k = 0; k < CC / 4; ++k) {
        float4 a = hv[k];
        float4 w = wr[k];
        acc += a.x * w.x + a.y * w.y + a.z * w.z + a.w * w.w;
    }
    g_wdyn[(size_t)b * W2ROWS + r] = acc;
}

// ---------------------------------------------------------------------------
// Kernel 3 v3: register-window sliding 3x3 stencil. No smem, no barriers.
// Thread = one 4-pixel-wide column strip of one plane, slides over 96 rows.
// Per row: 1 LDG.128 + 2 scalar halo LDG (L1 hits) + 36 FFMA + 1 STG.128.
// ---------------------------------------------------------------------------
struct Row6 { float4 c; float l, r; };

__device__ __forceinline__ Row6 load_row(const float* __restrict__ base,
                                         int y, int g) {
    Row6 o;
    const float* rp = base + y * HWD;
    o.c = *reinterpret_cast<const float4*>(rp + g * 4);
    // horizontal reflect: left of col 0 is col 1 (== c.y); right of col 95 is col 94 (== c.z)
    o.l = (g == 0)        ? o.c.y : rp[g * 4 - 1];
    o.r = (g == ROW4 - 1) ? o.c.z : rp[g * 4 + 4];
    return o;
}

__device__ __forceinline__ void row_fma(float4& acc, const Row6& rr,
                                        float wl, float wc, float wr) {
    acc.x += rr.l   * wl + rr.c.x * wc + rr.c.y * wr;
    acc.y += rr.c.x * wl + rr.c.y * wc + rr.c.z * wr;
    acc.z += rr.c.y * wl + rr.c.z * wc + rr.c.w * wr;
    acc.w += rr.c.z * wl + rr.c.w * wc + rr.r   * wr;
}

__global__ __launch_bounds__(256) void conv_kernel(const float* __restrict__ x,
                                                   float* __restrict__ out) {
    const int sid   = blockIdx.x * 256 + threadIdx.x;  // strip id [0, 8192*24)
    const int plane = sid / ROW4;
    const int g     = sid - plane * ROW4;

    const float* __restrict__ base = x + (size_t)plane * PLANE;
    float4* __restrict__ o4 =
        reinterpret_cast<float4*>(out + (size_t)plane * PLANE) + g;

    float w[KK];
    const float* __restrict__ wd = g_wdyn + (size_t)plane * KK;
#pragma unroll
    for (int i = 0; i < KK; ++i) w[i] = wd[i];   // broadcast within warp

    // window for row y: (prev, cur, nxt) = rows (reflect(y-1), y, reflect(y+1))
    Row6 cur  = load_row(base, 0, g);
    Row6 row1 = load_row(base, 1, g);
    Row6 prev = row1;     // reflect(-1) = 1
    Row6 nxt  = row1;

#pragma unroll 4
    for (int y = 0; y < HWD - 2; ++y) {
        Row6 pre = load_row(base, y + 2, g);   // prefetch 2 ahead
        float4 acc = make_float4(0.f, 0.f, 0.f, 0.f);
        row_fma(acc, prev, w[0], w[1], w[2]);
        row_fma(acc, cur,  w[3], w[4], w[5]);
        row_fma(acc, nxt,  w[6], w[7], w[8]);
        __stcs(&o4[y * ROW4], acc);
        prev = cur; cur = nxt; nxt = pre;
    }
    // y = 94: window (93, 94, 95)
    {
        float4 acc = make_float4(0.f, 0.f, 0.f, 0.f);
        row_fma(acc, prev, w[0], w[1], w[2]);
        row_fma(acc, cur,  w[3], w[4], w[5]);
        row_fma(acc, nxt,  w[6], w[7], w[8]);
        __stcs(&o4[(HWD - 2) * ROW4], acc);
        prev = cur; cur = nxt; nxt = prev;   // reflect(96) = 94
    }
    // y = 95: window (94, 95, 94)
    {
        float4 acc = make_float4(0.f, 0.f, 0.f, 0.f);
        row_fma(acc, prev, w[0], w[1], w[2]);
        row_fma(acc, cur,  w[3], w[4], w[5]);
        row_fma(acc, nxt,  w[6], w[7], w[8]);
        __stcs(&o4[(HWD - 1) * ROW4], acc);
    }
}

// ---------------------------------------------------------------------------
extern "C" void kernel_launch(void* const* d_in, const int* in_sizes, int n_in,
                              void* d_out, int out_size) {
    const float* x  = (const float*)d_in[0];   // (32,256,96,96)
    const float* w1 = (const float*)d_in[1];   // (256,256)
    const float* b1 = (const float*)d_in[2];   // (256,)
    const float* w2 = (const float*)d_in[3];   // (2304,256)
    const float* b2 = (const float*)d_in[4];   // (2304,)
    float* out = (float*)d_out;

    pool_kernel<<<NPLANES, 256>>>(x);
    dyn_kernel<<<dim3(KK, BB), 256>>>(w1, b1, w2, b2);
    conv_kernel<<<(NPLANES * ROW4) / 256, 256>>>(x, out);  // 768 blocks
}